// round 10
// baseline (speedup 1.0000x reference)
#include <cuda_runtime.h>

// -------------------------------------------------------------------------
// MaskedBilinearFullSymLoss — B=16, C=2, H=W=512, scalar f32 output.
// Persistent single-wave kernel (592 blocks = 4/SM x 148), atomic work
// stealing over 2048 units (unit = batch b x 4-row strip).
// Thread layout: tx (0..127) -> 4 consecutive cols, ty (0..1) -> 2-row group
// => 8 px/thread. Shifted windows via two aligned LDG.128 + compile-time
// window offset template (O = shift & 3). Tail tx >= 124 -> scalar path.
// -------------------------------------------------------------------------

#define HH 512
#define WW 512
#define TXV 124

__device__ double g_acc;            // zero-initialized
__device__ unsigned int g_ticket;   // zero-initialized
__device__ unsigned int g_work;     // zero-initialized

__device__ __forceinline__ float4 ld4(const float* __restrict__ p) {
    return *(const float4*)p;
}

struct Ctx {
    const float* __restrict__ g0;
    const float* __restrict__ g1;
    const float* __restrict__ mk;
    float wx1, wx2, wy1, wy2, w11, w12, w21, w22, sym_x, sym_y;
    int dx1, dy1, dy2, imax, jmax, j0;
};

// extract w[k] = v[O+k] (k=0..4) from two float4s; O compile-time
template<int O, int N>
__device__ __forceinline__ void win(float4 A, float4 Bv, float* w) {
    float v[8] = {A.x, A.y, A.z, A.w, Bv.x, Bv.y, Bv.z, Bv.w};
    #pragma unroll
    for (int k = 0; k < N; k++) w[k] = v[O + k];
}

// ---------- positive branch, vector: rows (ib, ib+1), cols j0..j0+3 ----------
template<int O>
__device__ __forceinline__ float pos_group(const Ctx& c, int ib) {
    const int base = c.j0 + (c.dx1 - O);   // 4-aligned, in-bounds for tx<TXV
    int os[3];
    #pragma unroll
    for (int t = 0; t < 3; t++) os[t] = min(ib + c.dy1 + t, HH - 1) * WW;

    float w0[3][5], w1[3][5];
    #pragma unroll
    for (int t = 0; t < 3; t++) {
        win<O,5>(ld4(c.g0 + os[t] + base), ld4(c.g0 + os[t] + base + 4), w0[t]);
        win<O,5>(ld4(c.g1 + os[t] + base), ld4(c.g1 + os[t] + base + 4), w1[t]);
    }

    float jv[4];
    #pragma unroll
    for (int k = 0; k < 4; k++) jv[k] = (c.j0 + k < c.jmax) ? 1.0f : 0.0f;

    float acc = 0.0f;
    #pragma unroll
    for (int r = 0; r < 2; r++) {
        const int oc = (ib + r) * WW + c.j0;
        float4 c0 = ld4(c.g0 + oc);
        float4 c1 = ld4(c.g1 + oc);
        float4 mq = ld4(c.mk + oc);
        const float rvv = (ib + r < c.imax) ? 1.0f : 0.0f;
        float cc0[4] = {c0.x, c0.y, c0.z, c0.w};
        float cc1[4] = {c1.x, c1.y, c1.z, c1.w};
        float mv[4]  = {mq.x, mq.y, mq.z, mq.w};
        #pragma unroll
        for (int k = 0; k < 4; k++) {
            float s0 = c.w11 * w0[r][k] + c.w12 * w0[r][k+1]
                     + c.w21 * w0[r+1][k] + c.w22 * w0[r+1][k+1];
            float s1 = c.w11 * w1[r][k] + c.w12 * w1[r][k+1]
                     + c.w21 * w1[r+1][k] + c.w22 * w1[r+1][k+1];
            float e = (cc0[k] - s0) * c.sym_y + (cc1[k] - s1) * c.sym_x;
            acc += (rvv * jv[k]) * mv[k] * e * e;
        }
    }
    return acc;
}

// ---------- positive branch, scalar tail ----------
__device__ __forceinline__ float pos_group_s(const Ctx& c, int ib) {
    int os[3];
    #pragma unroll
    for (int t = 0; t < 3; t++) os[t] = min(ib + c.dy1 + t, HH - 1) * WW;
    float w0[3][5], w1[3][5];
    #pragma unroll
    for (int t = 0; t < 3; t++)
        #pragma unroll
        for (int k = 0; k < 5; k++) {
            const int col = min(c.j0 + c.dx1 + k, WW - 1);
            w0[t][k] = c.g0[os[t] + col];
            w1[t][k] = c.g1[os[t] + col];
        }
    float acc = 0.0f;
    #pragma unroll
    for (int r = 0; r < 2; r++) {
        const int oc = (ib + r) * WW;
        const float rvv = (ib + r < c.imax) ? 1.0f : 0.0f;
        #pragma unroll
        for (int k = 0; k < 4; k++) {
            const int j = c.j0 + k;           // <= 511
            const float v = (j < c.jmax) ? rvv : 0.0f;
            float s0 = c.w11 * w0[r][k] + c.w12 * w0[r][k+1]
                     + c.w21 * w0[r+1][k] + c.w22 * w0[r+1][k+1];
            float s1 = c.w11 * w1[r][k] + c.w12 * w1[r][k+1]
                     + c.w21 * w1[r+1][k] + c.w22 * w1[r+1][k+1];
            float e = (c.g0[oc + j] - s0) * c.sym_y + (c.g1[oc + j] - s1) * c.sym_x;
            acc += v * c.mk[oc + j] * e * e;
        }
    }
    return acc;
}

// ---------- negative branch, vector ----------
template<int O2>
__device__ __forceinline__ float neg_group(const Ctx& c, int ib) {
    const int m2 = -c.dx1;                    // 0..8
    const int cbase = c.j0 + (m2 - O2);       // 4-aligned, in-bounds for tx<TXV

    // second-term rows ib..ib+2, window [cB0..cB0+3]
    float s0[3][4], s1[3][4];
    #pragma unroll
    for (int t = 0; t < 3; t++) {
        const int os = min(ib + t, HH - 1) * WW;
        win<O2,4>(ld4(c.g0 + os + cbase), ld4(c.g0 + os + cbase + 4), s0[t]);
        win<O2,4>(ld4(c.g1 + os + cbase), ld4(c.g1 + os + cbase + 4), s1[t]);
    }

    float jv[4];
    #pragma unroll
    for (int k = 0; k < 4; k++) jv[k] = (c.j0 + k < c.jmax) ? 1.0f : 0.0f;

    float acc = 0.0f;
    #pragma unroll
    for (int r = 0; r < 2; r++) {
        const int of = min(ib + c.dy2 + r, HH - 1) * WW;
        float4 F0 = ld4(c.g0 + of + c.j0);
        float4 F1 = ld4(c.g1 + of + c.j0);
        float z0 = c.g0[of + c.j0 + 4];       // tx<TXV: j0+4 <= 500
        float z1 = c.g1[of + c.j0 + 4];
        float mv[4];
        win<O2,4>(ld4(c.mk + of + cbase), ld4(c.mk + of + cbase + 4), mv);
        const float rvv = (ib + r < c.imax) ? 1.0f : 0.0f;
        float A0[5] = {F0.x, F0.y, F0.z, F0.w, z0};
        float A1[5] = {F1.x, F1.y, F1.z, F1.w, z1};
        #pragma unroll
        for (int k = 0; k < 4; k++) {
            float f0 = c.wx1 * A0[k] + c.wx2 * A0[k+1];
            float f1 = c.wx1 * A1[k] + c.wx2 * A1[k+1];
            float t0 = c.wy1 * s0[r+1][k] + c.wy2 * s0[r][k];
            float t1 = c.wy1 * s1[r+1][k] + c.wy2 * s1[r][k];
            float e = (f0 - t0) * c.sym_y + (f1 - t1) * c.sym_x;
            acc += (rvv * jv[k]) * mv[k] * e * e;
        }
    }
    return acc;
}

// ---------- negative branch, scalar tail ----------
__device__ __forceinline__ float neg_group_s(const Ctx& c, int ib) {
    const int m2 = -c.dx1;
    float s0[3][4], s1[3][4];
    #pragma unroll
    for (int t = 0; t < 3; t++) {
        const int os = min(ib + t, HH - 1) * WW;
        #pragma unroll
        for (int k = 0; k < 4; k++) {
            const int col = min(c.j0 + m2 + k, WW - 1);
            s0[t][k] = c.g0[os + col];
            s1[t][k] = c.g1[os + col];
        }
    }
    float acc = 0.0f;
    #pragma unroll
    for (int r = 0; r < 2; r++) {
        const int of = min(ib + c.dy2 + r, HH - 1) * WW;
        const float rvv = (ib + r < c.imax) ? 1.0f : 0.0f;
        #pragma unroll
        for (int k = 0; k < 4; k++) {
            const int j  = c.j0 + k;                   // <= 511
            const int jn = min(j + 1, WW - 1);         // reference clamp
            const int cB = min(j + m2, WW - 1);
            const float v = (j < c.jmax) ? rvv : 0.0f;
            float f0 = c.wx1 * c.g0[of + j] + c.wx2 * c.g0[of + jn];
            float f1 = c.wx1 * c.g1[of + j] + c.wx2 * c.g1[of + jn];
            float t0 = c.wy1 * s0[r+1][k] + c.wy2 * s0[r][k];
            float t1 = c.wy1 * s1[r+1][k] + c.wy2 * s1[r][k];
            float e = (f0 - t0) * c.sym_y + (f1 - t1) * c.sym_x;
            acc += v * c.mk[of + cB] * e * e;
        }
    }
    return acc;
}

__global__ __launch_bounds__(256, 4)
void loss_kernel(const float* __restrict__ grid,
                 const float* __restrict__ gt,
                 const float* __restrict__ gd,
                 const float* __restrict__ mask,
                 int B, unsigned int units, float* __restrict__ out)
{
    const int H = HH, W = WW;
    const int tid = threadIdx.x;
    const int tx = tid & 127;
    const int ty = tid >> 7;

    __shared__ unsigned int s_u;
    __shared__ float wsum[8];

    if (tid == 0) s_u = atomicAdd(&g_work, 1u);

    float facc = 0.0f;

    for (;;) {
        __syncthreads();
        const unsigned int u = s_u;
        __syncthreads();
        if (tid == 0) s_u = atomicAdd(&g_work, 1u);   // prefetch next unit
        if (u >= units) break;

        const int b  = (int)(u >> 7);          // 128 strips per batch item
        const int ib = (int)(u & 127u) * 4 + 2 * ty;

        const float dx = -8.0f * gt[2 * b + 0];
        const float dy =  8.0f * gt[2 * b + 1];

        Ctx c;
        c.sym_x = gd[2 * b + 0];
        c.sym_y = gd[2 * b + 1];
        const float dx1f = floorf(dx), dy1f = floorf(dy);
        c.dx1 = (int)dx1f;  c.dy1 = (int)dy1f;  c.dy2 = c.dy1 + 1;
        const int dx2 = c.dx1 + 1;
        c.wx1 = (dx1f + 1.0f) - dx;  c.wx2 = dx - dx1f;
        c.wy1 = (dy1f + 1.0f) - dy;  c.wy2 = dy - dy1f;
        c.w11 = c.wy1 * c.wx1;  c.w12 = c.wy1 * c.wx2;
        c.w21 = c.wy2 * c.wx1;  c.w22 = c.wy2 * c.wx2;
        c.g0 = grid + (size_t)(2 * b + 0) * H * W;
        c.g1 = grid + (size_t)(2 * b + 1) * H * W;
        c.mk = mask + (size_t)b * H * W;
        c.imax = H - c.dy2;
        c.j0 = 4 * tx;

        float uacc;
        float cnt;
        if (dx > 0.0f) {
            c.jmax = W - dx2;
            cnt = (float)c.imax * (float)c.jmax;
            if (tx < TXV) {
                switch (c.dx1 & 3) {
                    case 0:  uacc = pos_group<0>(c, ib); break;
                    case 1:  uacc = pos_group<1>(c, ib); break;
                    case 2:  uacc = pos_group<2>(c, ib); break;
                    default: uacc = pos_group<3>(c, ib); break;
                }
            } else uacc = pos_group_s(c, ib);
        } else {
            c.jmax = W + c.dx1;
            cnt = (float)c.imax * (float)c.jmax;
            if (tx < TXV) {
                switch ((-c.dx1) & 3) {
                    case 0:  uacc = neg_group<0>(c, ib); break;
                    case 1:  uacc = neg_group<1>(c, ib); break;
                    case 2:  uacc = neg_group<2>(c, ib); break;
                    default: uacc = neg_group<3>(c, ib); break;
                }
            } else uacc = neg_group_s(c, ib);
        }
        facc += uacc * (1.0f / cnt);
    }

    // ---- block reduction (8 warps)
    #pragma unroll
    for (int o = 16; o > 0; o >>= 1)
        facc += __shfl_down_sync(0xFFFFFFFFu, facc, o);

    const int lane = tid & 31;
    const int warp = tid >> 5;
    if (lane == 0) wsum[warp] = facc;
    __syncthreads();

    if (tid == 0) {
        float s = 0.0f;
        #pragma unroll
        for (int k = 0; k < 8; k++) s += wsum[k];
        atomicAdd(&g_acc, (double)s);

        __threadfence();
        unsigned int prev = atomicInc(&g_ticket, (unsigned int)gridDim.x - 1u);
        if (prev == (unsigned int)gridDim.x - 1u) {
            double total = atomicAdd(&g_acc, 0.0);    // atomic read
            out[0] = (float)(total / (double)B);
            g_acc  = 0.0;                             // reset for next replay
            g_work = 0u;
            __threadfence();
        }
    }
}

extern "C" void kernel_launch(void* const* d_in, const int* in_sizes, int n_in,
                              void* d_out, int out_size)
{
    const float* grid = (const float*)d_in[0];
    const float* gt   = (const float*)d_in[1];
    const float* gd   = (const float*)d_in[2];
    const float* mask = (const float*)d_in[3];
    float* out = (float*)d_out;

    const int B = in_sizes[1] / 2;            // gt_sym_axis is (B, 2)
    const unsigned int units = (unsigned int)(128 * B);

    loss_kernel<<<592, 256>>>(grid, gt, gd, mask, B, units, out);
}

// round 11
// speedup vs baseline: 1.1555x; 1.1555x over previous
#include <cuda_runtime.h>

// -------------------------------------------------------------------------
// MaskedBilinearFullSymLoss — B=16, C=2, H=W=512, scalar f32 output.
// Persistent single-wave kernel (888 blocks = 6/SM x 148) with atomic work
// stealing over 2048 units (unit = one batch b x 4-row strip). Body = R9:
// float2 loads, parity-templated shifted windows, 4-row sharing, 8 px/thr.
// -------------------------------------------------------------------------

#define HH 512
#define WW 512
#define NPERSIST 888u

__device__ double g_acc;            // zero-initialized
__device__ unsigned int g_ticket;   // zero-initialized
__device__ unsigned int g_work;     // zero-initialized

__device__ __forceinline__ float2 ld2(const float* __restrict__ p) {
    return *(const float2*)p;
}

struct Ctx {
    const float* __restrict__ g0;
    const float* __restrict__ g1;
    const float* __restrict__ mk;
    float wx1, wx2, wy1, wy2, w11, w12, w21, w22, sym_x, sym_y;
    int dx1, dy1, dy2, imax, jmax, i0, j0;
};

// 3-float shifted window [ja, ja+1, ja+2]; P = ja parity. Clamped values are
// only consumed with a zero validity factor.
template<int P>
__device__ __forceinline__ void ldwin(const float* __restrict__ row, int ja,
                                      float& x0, float& x1, float& x2) {
    if (P == 0) {
        float2 v = ld2(row + min(ja, WW - 2));
        float  s = row[min(ja + 2, WW - 1)];
        x0 = v.x; x1 = v.y; x2 = s;
    } else {
        float2 a = ld2(row + min(ja - 1, WW - 2));
        float2 b = ld2(row + min(ja + 1, WW - 2));
        x0 = a.y; x1 = b.x; x2 = b.y;
    }
}

// 2-float window [c, c+1]; Q = c parity.
template<int Q>
__device__ __forceinline__ void ldpair(const float* __restrict__ row, int c,
                                       float& y0, float& y1) {
    if (Q == 0) {
        float2 v = ld2(row + min(c, WW - 2));
        y0 = v.x; y1 = v.y;
    } else {
        y0 = row[min(c,     WW - 1)];
        y1 = row[min(c + 1, WW - 1)];
    }
}

// ---- positive branch: output rows (ib, ib+1), cols (j0, j0+1)
template<int P>
__device__ __forceinline__ float pos_pair(const Ctx& c, int ib) {
    const int ja = c.j0 + c.dx1;
    int os[3];
    #pragma unroll
    for (int t = 0; t < 3; t++) os[t] = min(ib + c.dy1 + t, HH - 1) * WW;

    float X0[3], X1[3], X2[3];
    float Y0[3], Y1[3], Y2[3];
    #pragma unroll
    for (int t = 0; t < 3; t++) {
        ldwin<P>(c.g0 + os[t], ja, X0[t], X1[t], X2[t]);
        ldwin<P>(c.g1 + os[t], ja, Y0[t], Y1[t], Y2[t]);
    }

    const float jv0 = (c.j0     < c.jmax) ? 1.0f : 0.0f;
    const float jv1 = (c.j0 + 1 < c.jmax) ? 1.0f : 0.0f;

    float acc = 0.0f;
    #pragma unroll
    for (int r = 0; r < 2; r++) {
        const int oc = (ib + r) * WW + c.j0;     // always in-bounds
        float2 c0 = ld2(c.g0 + oc);
        float2 c1 = ld2(c.g1 + oc);
        float2 mm = ld2(c.mk + oc);
        const float rvv = (ib + r < c.imax) ? 1.0f : 0.0f;
        mm.x *= rvv * jv0;
        mm.y *= rvv * jv1;
        float s0 = c.w11 * X0[r] + c.w12 * X1[r] + c.w21 * X0[r+1] + c.w22 * X1[r+1];
        float s1 = c.w11 * Y0[r] + c.w12 * Y1[r] + c.w21 * Y0[r+1] + c.w22 * Y1[r+1];
        float e0 = (c0.x - s0) * c.sym_y + (c1.x - s1) * c.sym_x;
        acc += mm.x * e0 * e0;
        float t0 = c.w11 * X1[r] + c.w12 * X2[r] + c.w21 * X1[r+1] + c.w22 * X2[r+1];
        float t1 = c.w11 * Y1[r] + c.w12 * Y2[r] + c.w21 * Y1[r+1] + c.w22 * Y2[r+1];
        float e1 = (c0.y - t0) * c.sym_y + (c1.y - t1) * c.sym_x;
        acc += mm.y * e1 * e1;
    }
    return acc;
}

// ---- negative branch: rows (ib, ib+1), cols (j0, j0+1)
template<int Q>
__device__ __forceinline__ float neg_pair(const Ctx& c, int ib) {
    const int m2  = -c.dx1;            // >= 0
    const int cB0 = c.j0 + m2;

    float S0a[3], S0b[3], S1a[3], S1b[3];
    #pragma unroll
    for (int t = 0; t < 3; t++) {
        const int os = min(ib + t, HH - 1) * WW;
        ldpair<Q>(c.g0 + os, cB0, S0a[t], S0b[t]);
        ldpair<Q>(c.g1 + os, cB0, S1a[t], S1b[t]);
    }

    const float jv0 = (c.j0     < c.jmax) ? 1.0f : 0.0f;
    const float jv1 = (c.j0 + 1 < c.jmax) ? 1.0f : 0.0f;

    float acc = 0.0f;
    #pragma unroll
    for (int r = 0; r < 2; r++) {
        const int of = min(ib + c.dy2 + r, HH - 1) * WW;
        float2 v0 = ld2(c.g0 + of + c.j0);
        float2 v1 = ld2(c.g1 + of + c.j0);
        float z0 = c.g0[of + min(c.j0 + 2, WW - 1)];
        float z1 = c.g1[of + min(c.j0 + 2, WW - 1)];
        float mx, my;
        ldpair<Q>(c.mk + of, cB0, mx, my);
        const float rvv = (ib + r < c.imax) ? 1.0f : 0.0f;
        mx *= rvv * jv0;
        my *= rvv * jv1;
        float f0 = c.wx1 * v0.x + c.wx2 * v0.y;
        float f1 = c.wx1 * v1.x + c.wx2 * v1.y;
        float s0 = c.wy1 * S0a[r+1] + c.wy2 * S0a[r];
        float s1 = c.wy1 * S1a[r+1] + c.wy2 * S1a[r];
        float e0 = (f0 - s0) * c.sym_y + (f1 - s1) * c.sym_x;
        acc += mx * e0 * e0;
        float g0v = c.wx1 * v0.y + c.wx2 * z0;
        float g1v = c.wx1 * v1.y + c.wx2 * z1;
        float u0 = c.wy1 * S0b[r+1] + c.wy2 * S0b[r];
        float u1 = c.wy1 * S1b[r+1] + c.wy2 * S1b[r];
        float e1 = (g0v - u0) * c.sym_y + (g1v - u1) * c.sym_x;
        acc += my * e1 * e1;
    }
    return acc;
}

__global__ __launch_bounds__(256, 6)
void loss_kernel(const float* __restrict__ grid,
                 const float* __restrict__ gt,
                 const float* __restrict__ gd,
                 const float* __restrict__ mask,
                 int B, unsigned int units, float* __restrict__ out)
{
    const int H = HH, W = WW;
    const int tid = threadIdx.x;

    __shared__ unsigned int s_u;
    __shared__ float wsum[8];

    if (tid == 0) s_u = atomicAdd(&g_work, 1u);

    float facc = 0.0f;

    for (;;) {
        __syncthreads();
        const unsigned int u = s_u;
        __syncthreads();
        if (tid == 0) s_u = atomicAdd(&g_work, 1u);   // prefetch next unit
        if (u >= units) break;

        const int b  = (int)(u >> 7);         // 128 strips per batch item
        const int i0 = (int)(u & 127u) * 4;

        const float dx = -8.0f * gt[2 * b + 0];
        const float dy =  8.0f * gt[2 * b + 1];

        Ctx c;
        c.sym_x = gd[2 * b + 0];
        c.sym_y = gd[2 * b + 1];
        const float dx1f = floorf(dx), dy1f = floorf(dy);
        c.dx1 = (int)dx1f;  c.dy1 = (int)dy1f;  c.dy2 = c.dy1 + 1;
        const int dx2 = c.dx1 + 1;
        c.wx1 = (dx1f + 1.0f) - dx;  c.wx2 = dx - dx1f;
        c.wy1 = (dy1f + 1.0f) - dy;  c.wy2 = dy - dy1f;
        c.w11 = c.wy1 * c.wx1;  c.w12 = c.wy1 * c.wx2;
        c.w21 = c.wy2 * c.wx1;  c.w22 = c.wy2 * c.wx2;
        c.g0 = grid + (size_t)(2 * b + 0) * H * W;
        c.g1 = grid + (size_t)(2 * b + 1) * H * W;
        c.mk = mask + (size_t)b * H * W;
        c.imax = H - c.dy2;
        c.i0 = i0;
        c.j0 = 2 * tid;

        float uacc;
        float cnt;
        if (dx > 0.0f) {
            c.jmax = W - dx2;
            cnt = (float)c.imax * (float)c.jmax;
            if (c.dx1 & 1) uacc = pos_pair<1>(c, i0) + pos_pair<1>(c, i0 + 2);
            else           uacc = pos_pair<0>(c, i0) + pos_pair<0>(c, i0 + 2);
        } else {
            c.jmax = W + c.dx1;
            cnt = (float)c.imax * (float)c.jmax;
            if ((-c.dx1) & 1) uacc = neg_pair<1>(c, i0) + neg_pair<1>(c, i0 + 2);
            else              uacc = neg_pair<0>(c, i0) + neg_pair<0>(c, i0 + 2);
        }
        facc += uacc * (1.0f / cnt);
    }

    // ---- block reduction (8 warps)
    #pragma unroll
    for (int o = 16; o > 0; o >>= 1)
        facc += __shfl_down_sync(0xFFFFFFFFu, facc, o);

    const int lane = tid & 31;
    const int warp = tid >> 5;
    if (lane == 0) wsum[warp] = facc;
    __syncthreads();

    if (tid == 0) {
        float s = 0.0f;
        #pragma unroll
        for (int k = 0; k < 8; k++) s += wsum[k];
        atomicAdd(&g_acc, (double)s);

        __threadfence();
        unsigned int prev = atomicInc(&g_ticket, (unsigned int)gridDim.x - 1u);
        if (prev == (unsigned int)gridDim.x - 1u) {
            double total = atomicAdd(&g_acc, 0.0);    // atomic read
            out[0] = (float)(total / (double)B);
            g_acc  = 0.0;                             // reset for next replay
            g_work = 0u;
            __threadfence();
        }
    }
}

extern "C" void kernel_launch(void* const* d_in, const int* in_sizes, int n_in,
                              void* d_out, int out_size)
{
    const float* grid = (const float*)d_in[0];
    const float* gt   = (const float*)d_in[1];
    const float* gd   = (const float*)d_in[2];
    const float* mask = (const float*)d_in[3];
    float* out = (float*)d_out;

    const int B = in_sizes[1] / 2;            // gt_sym_axis is (B, 2)
    const unsigned int units = (unsigned int)(128 * B);

    loss_kernel<<<NPERSIST, 256>>>(grid, gt, gd, mask, B, units, out);
}